// round 1
// baseline (speedup 1.0000x reference)
#include <cuda_runtime.h>
#include <cstddef>
#include <cstdint>

// ---------------------------------------------------------------------------
// Problem constants
// ---------------------------------------------------------------------------
#define BB 4
#define LL 2048
#define DD 1024
#define HH 16
#define DK 64
#define DV 64
#define DFF 4096
#define ROWS (BB * LL)          // 8192
#define Y_ELEMS ((size_t)ROWS * DD)              // 8,388,608
#define ATTN_ELEMS ((size_t)BB * HH * LL * LL)   // 268,435,456

// ---------------------------------------------------------------------------
// Scratch (device globals: allocation-free rule)
// ---------------------------------------------------------------------------
__device__ float g_x[ROWS * DD];
__device__ float g_q[ROWS * DD];
__device__ float g_k[ROWS * DD];
__device__ float g_v[ROWS * DD];
__device__ float g_o[ROWS * DD];
__device__ float g_y[ROWS * DD];
__device__ float g_z[ROWS * DD];
__device__ float g_h[ROWS * DFF];

// ---------------------------------------------------------------------------
// f32x2 helpers (Blackwell paired fp32 FMA)
// ---------------------------------------------------------------------------
__device__ __forceinline__ unsigned long long pack2(float a, float b) {
    unsigned long long r;
    unsigned int ia = __float_as_uint(a), ib = __float_as_uint(b);
    asm("mov.b64 %0, {%1, %2};" : "=l"(r) : "r"(ia), "r"(ib));
    return r;
}
__device__ __forceinline__ unsigned long long fma2(unsigned long long a,
                                                   unsigned long long b,
                                                   unsigned long long c) {
    unsigned long long d;
    asm("fma.rn.f32x2 %0, %1, %2, %3;" : "=l"(d) : "l"(a), "l"(b), "l"(c));
    return d;
}
__device__ __forceinline__ float2 unpack2(unsigned long long v) {
    unsigned int lo, hi;
    asm("mov.b64 {%0, %1}, %2;" : "=r"(lo), "=r"(hi) : "l"(v));
    float2 r;
    r.x = __uint_as_float(lo);
    r.y = __uint_as_float(hi);
    return r;
}

// ---------------------------------------------------------------------------
// Fast software exp (avoid MUFU throughput wall: 537M exps would be ~4ms)
// x <= 0 expected; clamp handles masked -1e9.
// ---------------------------------------------------------------------------
__device__ __forceinline__ float fast_exp(float x) {
    x = fmaxf(x, -87.0f);
    float t = x * 1.4426950408889634f;   // x * log2(e)
    float fi = floorf(t);
    float y = fmaf(fi, -0.6931471805599453f, x);   // x - fi*ln2, in [0, ln2)
    int i = (int)fi;                                // [-126, 0]
    float p = 1.9841270e-4f;
    p = fmaf(p, y, 1.3888889e-3f);
    p = fmaf(p, y, 8.3333333e-3f);
    p = fmaf(p, y, 4.1666667e-2f);
    p = fmaf(p, y, 1.6666666e-1f);
    p = fmaf(p, y, 0.5f);
    p = fmaf(p, y, 1.0f);
    p = fmaf(p, y, 1.0f);
    return __int_as_float((i + 127) << 23) * p;
}

// ---------------------------------------------------------------------------
// LayerNorm: one block per row of 1024
// ---------------------------------------------------------------------------
__global__ void ln_kernel(const float* __restrict__ in, float* __restrict__ out,
                          const float* __restrict__ gam, const float* __restrict__ bet) {
    int row = blockIdx.x;
    int tid = threadIdx.x;                    // 256 threads, 4 elems each
    const float* x = in + (size_t)row * DD;
    float4 v = *(const float4*)(x + tid * 4);
    float s = v.x + v.y + v.z + v.w;
    float ss = v.x * v.x + v.y * v.y + v.z * v.z + v.w * v.w;
    __shared__ float red[16];
#pragma unroll
    for (int o = 16; o; o >>= 1) {
        s += __shfl_xor_sync(0xffffffffu, s, o);
        ss += __shfl_xor_sync(0xffffffffu, ss, o);
    }
    if ((tid & 31) == 0) { red[(tid >> 5) * 2] = s; red[(tid >> 5) * 2 + 1] = ss; }
    __syncthreads();
    float mu = 0.f, m2 = 0.f;
#pragma unroll
    for (int w = 0; w < 8; w++) { mu += red[2 * w]; m2 += red[2 * w + 1]; }
    mu *= (1.0f / DD);
    float var = m2 * (1.0f / DD) - mu * mu;
    float rstd = rsqrtf(var + 1e-6f);
    float4 gg = *(const float4*)(gam + tid * 4);
    float4 bb = *(const float4*)(bet + tid * 4);
    float4 o4;
    o4.x = (v.x - mu) * rstd * gg.x + bb.x;
    o4.y = (v.y - mu) * rstd * gg.y + bb.y;
    o4.z = (v.z - mu) * rstd * gg.z + bb.z;
    o4.w = (v.w - mu) * rstd * gg.w + bb.w;
    *(float4*)(out + (size_t)row * DD + tid * 4) = o4;
}

// ---------------------------------------------------------------------------
// Generic tiled GEMM, fp32 with f32x2 accumulation.
//   BT=true : C[M,N] = A[M,K] * B[N,K]^T   (both K-major, "NT")
//   BT=false: C[M,N] = A[M,K] * B[K,N]     ("NN")
// Optional bias (len N), residual (same layout as C), relu.
// Batched via blockIdx.z: z -> (zo = z/zInner, zi = z%zInner) pointer offsets.
// BM=128, BK=16, 256 threads; BN in {128, 64}.
// ---------------------------------------------------------------------------
#define TBM 128
#define TBK 16

template <int BN, bool BT>
__global__ void __launch_bounds__(256, 2)
gemm_kernel(const float* __restrict__ A, const float* __restrict__ B,
            float* __restrict__ C,
            const float* __restrict__ bias, const float* __restrict__ resid,
            int relu,
            int M, int N, int K, int lda, int ldb, int ldc,
            long long sAo, long long sAi, long long sBo, long long sBi,
            long long sCo, long long sCi, int zInner) {
    constexpr int NG = BN / 64;
    __shared__ float As[TBK][TBM + 4];
    __shared__ float Bs[TBK][BN + 4];
    int tid = threadIdx.x;
    int z = blockIdx.z;
    int zo = z / zInner, zi = z % zInner;
    A += zo * sAo + zi * sAi;
    B += zo * sBo + zi * sBi;
    C += zo * sCo + zi * sCi;
    const float* Rp = resid ? (resid + zo * sCo + zi * sCi) : nullptr;
    int bm = blockIdx.y * TBM;
    int bn = blockIdx.x * BN;
    int rm = (tid >> 4) * 8;
    int cn = (tid & 15) * 4;

    unsigned long long acc[8][2 * NG];
#pragma unroll
    for (int i = 0; i < 8; i++)
#pragma unroll
        for (int j = 0; j < 2 * NG; j++) acc[i][j] = 0ull;

    for (int k0 = 0; k0 < K; k0 += TBK) {
        // ---- load A tile (transpose into As[k][m]) ----
#pragma unroll
        for (int t = 0; t < 2; t++) {
            int f = tid * 2 + t;
            int row = f >> 2;
            int c4 = (f & 3) * 4;
            float4 v = *(const float4*)(A + (size_t)(bm + row) * lda + k0 + c4);
            As[c4 + 0][row] = v.x;
            As[c4 + 1][row] = v.y;
            As[c4 + 2][row] = v.z;
            As[c4 + 3][row] = v.w;
        }
        // ---- load B tile ----
        if constexpr (BT) {
            // B[N,K]: transpose into Bs[k][n]
#pragma unroll
            for (int t = 0; t < BN / 64; t++) {
                int f = tid * (BN / 64) + t;
                int row = f >> 2;
                int c4 = (f & 3) * 4;
                float4 v = *(const float4*)(B + (size_t)(bn + row) * ldb + k0 + c4);
                Bs[c4 + 0][row] = v.x;
                Bs[c4 + 1][row] = v.y;
                Bs[c4 + 2][row] = v.z;
                Bs[c4 + 3][row] = v.w;
            }
        } else {
            // B[K,N]: direct copy rows k0..k0+15
#pragma unroll
            for (int t = 0; t < BN / 64; t++) {
                int f = tid * (BN / 64) + t;
                int row = f / (BN / 4);
                int c4 = (f % (BN / 4)) * 4;
                float4 v = *(const float4*)(B + (size_t)(k0 + row) * ldb + bn + c4);
                *(float4*)&Bs[row][c4] = v;
            }
        }
        __syncthreads();
        // ---- compute ----
#pragma unroll
        for (int kk = 0; kk < TBK; kk++) {
            float4 a0 = *(const float4*)&As[kk][rm];
            float4 a1 = *(const float4*)&As[kk][rm + 4];
            unsigned long long av[8];
            av[0] = pack2(a0.x, a0.x);
            av[1] = pack2(a0.y, a0.y);
            av[2] = pack2(a0.z, a0.z);
            av[3] = pack2(a0.w, a0.w);
            av[4] = pack2(a1.x, a1.x);
            av[5] = pack2(a1.y, a1.y);
            av[6] = pack2(a1.z, a1.z);
            av[7] = pack2(a1.w, a1.w);
#pragma unroll
            for (int g = 0; g < NG; g++) {
                float4 b0 = *(const float4*)&Bs[kk][cn + g * 64];
                unsigned long long bb0 = pack2(b0.x, b0.y);
                unsigned long long bb1 = pack2(b0.z, b0.w);
#pragma unroll
                for (int i = 0; i < 8; i++) {
                    acc[i][2 * g]     = fma2(av[i], bb0, acc[i][2 * g]);
                    acc[i][2 * g + 1] = fma2(av[i], bb1, acc[i][2 * g + 1]);
                }
            }
        }
        __syncthreads();
    }
    // ---- epilogue ----
#pragma unroll
    for (int i = 0; i < 8; i++) {
        int row = bm + rm + i;
#pragma unroll
        for (int g = 0; g < NG; g++) {
            int col = bn + cn + g * 64;
            float2 p0 = unpack2(acc[i][2 * g]);
            float2 p1 = unpack2(acc[i][2 * g + 1]);
            float4 v = make_float4(p0.x, p0.y, p1.x, p1.y);
            if (bias) {
                v.x += bias[col];
                v.y += bias[col + 1];
                v.z += bias[col + 2];
                v.w += bias[col + 3];
            }
            if (Rp) {
                float4 r = *(const float4*)(Rp + (size_t)row * ldc + col);
                v.x += r.x; v.y += r.y; v.z += r.z; v.w += r.w;
            }
            if (relu) {
                v.x = fmaxf(v.x, 0.f); v.y = fmaxf(v.y, 0.f);
                v.z = fmaxf(v.z, 0.f); v.w = fmaxf(v.w, 0.f);
            }
            *(float4*)(C + (size_t)row * ldc + col) = v;
        }
    }
}

// ---------------------------------------------------------------------------
// In-place prior/mask/softmax over the attn buffer.
// One block per (q, b); loops over all 16 heads so prior/mask are read once.
// ---------------------------------------------------------------------------
__device__ __forceinline__ float bred(float v, float* red, bool domax) {
#pragma unroll
    for (int o = 16; o; o >>= 1) {
        float t = __shfl_xor_sync(0xffffffffu, v, o);
        v = domax ? fmaxf(v, t) : v + t;
    }
    if ((threadIdx.x & 31) == 0) red[threadIdx.x >> 5] = v;
    __syncthreads();
    float r = red[0];
#pragma unroll
    for (int i = 1; i < 8; i++) r = domax ? fmaxf(r, red[i]) : r + red[i];
    __syncthreads();
    return r;
}

__global__ void softmax_kernel(float* __restrict__ attn,
                               const float* __restrict__ prior,
                               const int* __restrict__ mask) {
    int q = blockIdx.x;
    int b = blockIdx.y;
    int tid = threadIdx.x;        // 256 threads; 8 elems each (two float4 halves)
    __shared__ float red[8];

    const float* pr = prior + ((size_t)b * LL + q) * LL;
    float4 p0 = *(const float4*)(pr + tid * 4);
    float4 p1 = *(const float4*)(pr + 1024 + tid * 4);
    const int* mp = mask + b * LL;
    int4 m0 = *(const int4*)(mp + tid * 4);
    int4 m1 = *(const int4*)(mp + 1024 + tid * 4);

    float f[8];
    f[0] = 0.125f * p0.x; f[1] = 0.125f * p0.y; f[2] = 0.125f * p0.z; f[3] = 0.125f * p0.w;
    f[4] = 0.125f * p1.x; f[5] = 0.125f * p1.y; f[6] = 0.125f * p1.z; f[7] = 0.125f * p1.w;
    int mk[8] = {m0.x, m0.y, m0.z, m0.w, m1.x, m1.y, m1.z, m1.w};

    for (int h = 0; h < HH; h++) {
        float* srow = attn + (((size_t)(b * HH + h) * LL + q) * LL);
        float4 s0 = *(const float4*)(srow + tid * 4);
        float4 s1 = *(const float4*)(srow + 1024 + tid * 4);
        float v[8];
        v[0] = mk[0] ? s0.x * f[0] : -1e9f;
        v[1] = mk[1] ? s0.y * f[1] : -1e9f;
        v[2] = mk[2] ? s0.z * f[2] : -1e9f;
        v[3] = mk[3] ? s0.w * f[3] : -1e9f;
        v[4] = mk[4] ? s1.x * f[4] : -1e9f;
        v[5] = mk[5] ? s1.y * f[5] : -1e9f;
        v[6] = mk[6] ? s1.z * f[6] : -1e9f;
        v[7] = mk[7] ? s1.w * f[7] : -1e9f;
        float mloc = v[0];
#pragma unroll
        for (int i = 1; i < 8; i++) mloc = fmaxf(mloc, v[i]);
        float M = bred(mloc, red, true);
        float e[8];
        float ssum = 0.f;
#pragma unroll
        for (int i = 0; i < 8; i++) { e[i] = fast_exp(v[i] - M); ssum += e[i]; }
        float S = bred(ssum, red, false);
        float inv = 1.0f / S;
        float4 o0 = make_float4(e[0] * inv, e[1] * inv, e[2] * inv, e[3] * inv);
        float4 o1 = make_float4(e[4] * inv, e[5] * inv, e[6] * inv, e[7] * inv);
        *(float4*)(srow + tid * 4) = o0;
        *(float4*)(srow + 1024 + tid * 4) = o1;
    }
}

// ---------------------------------------------------------------------------
// Launch
// ---------------------------------------------------------------------------
extern "C" void kernel_launch(void* const* d_in, const int* in_sizes, int n_in,
                              void* d_out, int out_size) {
    const float* src    = (const float*)d_in[0];
    const int*   mask   = (const int*)d_in[1];
    const float* prior  = (const float*)d_in[2];
    const float* ln1_g  = (const float*)d_in[3];
    const float* ln1_b  = (const float*)d_in[4];
    const float* wq     = (const float*)d_in[5];
    const float* wk     = (const float*)d_in[6];
    const float* wv     = (const float*)d_in[7];
    const float* fc_w   = (const float*)d_in[8];
    const float* ln2_g  = (const float*)d_in[9];
    const float* ln2_b  = (const float*)d_in[10];
    const float* w1_w   = (const float*)d_in[11];
    const float* w1_b   = (const float*)d_in[12];
    const float* w2_w   = (const float*)d_in[13];
    const float* w2_b   = (const float*)d_in[14];

    float* yout = (float*)d_out;
    float* attn = yout + Y_ELEMS;

    float* xb; cudaGetSymbolAddress((void**)&xb, g_x);
    float* qb; cudaGetSymbolAddress((void**)&qb, g_q);
    float* kb; cudaGetSymbolAddress((void**)&kb, g_k);
    float* vb; cudaGetSymbolAddress((void**)&vb, g_v);
    float* ob; cudaGetSymbolAddress((void**)&ob, g_o);
    float* yb; cudaGetSymbolAddress((void**)&yb, g_y);
    float* zb; cudaGetSymbolAddress((void**)&zb, g_z);
    float* hb; cudaGetSymbolAddress((void**)&hb, g_h);

    // 1) LN1
    ln_kernel<<<ROWS, 256>>>(src, xb, ln1_g, ln1_b);

    // 2) Q,K,V projections: [8192,1024] x [1024,1024]^T
    dim3 gProj(DD / 128, ROWS / 128, 1);
    gemm_kernel<128, true><<<gProj, 256>>>(xb, wq, qb, nullptr, nullptr, 0,
        ROWS, DD, DD, DD, DD, DD, 0, 0, 0, 0, 0, 0, 1);
    gemm_kernel<128, true><<<gProj, 256>>>(xb, wk, kb, nullptr, nullptr, 0,
        ROWS, DD, DD, DD, DD, DD, 0, 0, 0, 0, 0, 0, 1);
    gemm_kernel<128, true><<<gProj, 256>>>(xb, wv, vb, nullptr, nullptr, 0,
        ROWS, DD, DD, DD, DD, DD, 0, 0, 0, 0, 0, 0, 1);

    // 3) Raw scores S = q . k  (per b,h), written straight into attn region
    {
        dim3 g(LL / 128, LL / 128, BB * HH);
        gemm_kernel<128, true><<<g, 256>>>(qb, kb, attn, nullptr, nullptr, 0,
            LL, LL, DK, DD, DD, LL,
            (long long)LL * DD, (long long)DK,            // A: per-b, per-h
            (long long)LL * DD, (long long)DK,            // B: per-b, per-h
            (long long)HH * LL * LL, (long long)LL * LL,  // C: per-b, per-h
            HH);
    }

    // 4) prior * mask * softmax (in place)
    softmax_kernel<<<dim3(LL, BB), 256>>>(attn, prior, mask);

    // 5) O = P @ V : [2048,2048] x [2048,64] per (b,h), NN
    {
        dim3 g(1, LL / 128, BB * HH);
        gemm_kernel<64, false><<<g, 256>>>(attn, vb, ob, nullptr, nullptr, 0,
            LL, DV, LL, LL, DD, DD,
            (long long)HH * LL * LL, (long long)LL * LL,  // A
            (long long)LL * DD, (long long)DV,            // B
            (long long)LL * DD, (long long)DV,            // C
            HH);
    }

    // 6) y = O @ fc_w^T + src
    gemm_kernel<128, true><<<gProj, 256>>>(ob, fc_w, yb, nullptr, src, 0,
        ROWS, DD, DD, DD, DD, DD, 0, 0, 0, 0, 0, 0, 1);

    // 7) LN2
    ln_kernel<<<ROWS, 256>>>(yb, zb, ln2_g, ln2_b);

    // 8) h = relu(z @ w1^T + b1)
    {
        dim3 g(DFF / 128, ROWS / 128, 1);
        gemm_kernel<128, true><<<g, 256>>>(zb, w1_w, hb, w1_b, nullptr, 1,
            ROWS, DFF, DD, DD, DD, DFF, 0, 0, 0, 0, 0, 0, 1);
    }

    // 9) y_out = h @ w2^T + b2 + y   (written straight to d_out)
    gemm_kernel<128, true><<<gProj, 256>>>(hb, w2_w, yout, w2_b, yb, 0,
        ROWS, DD, DFF, DFF, DFF, DD, 0, 0, 0, 0, 0, 0, 1);
}

// round 3
// speedup vs baseline: 2.7091x; 2.7091x over previous
#include <cuda_runtime.h>
#include <cstddef>
#include <cstdint>

// ---------------------------------------------------------------------------
// Problem constants
// ---------------------------------------------------------------------------
#define BB 4
#define LL 2048
#define DD 1024
#define HH 16
#define DK 64
#define DV 64
#define DFF 4096
#define ROWS (BB * LL)          // 8192
#define Y_ELEMS ((size_t)ROWS * DD)

// ---------------------------------------------------------------------------
// Scratch (device globals: allocation-free rule)
// ---------------------------------------------------------------------------
__device__ float g_x[ROWS * DD];
__device__ float g_q[ROWS * DD];
__device__ float g_k[ROWS * DD];
__device__ float g_vt[ROWS * DD];          // V transposed: [H*DV, ROWS]
__device__ float g_o[ROWS * DD];
__device__ float g_y[ROWS * DD];
__device__ float g_z[ROWS * DD];
__device__ float g_h[ROWS * DFF];
// tf32-rounded weights
__device__ float g_wq[DD * DD];
__device__ float g_wk[DD * DD];
__device__ float g_wv[DD * DD];
__device__ float g_fc[DD * DD];
__device__ float g_w1[DFF * DD];
__device__ float g_w2[DD * DFF];

// ---------------------------------------------------------------------------
// Helpers
// ---------------------------------------------------------------------------
__device__ __forceinline__ uint32_t smem_u32(const void* p) {
    uint32_t a;
    asm("{ .reg .u64 t; cvta.to.shared.u64 t, %1; cvt.u32.u64 %0, t; }" : "=r"(a) : "l"(p));
    return a;
}
__device__ __forceinline__ float tf32r(float x) {
    unsigned u = __float_as_uint(x), o;
    asm("cvt.rna.tf32.f32 %0, %1;" : "=r"(o) : "r"(u));
    return __uint_as_float(o);
}
__device__ __forceinline__ void cp16(uint32_t s, const void* g) {
    asm volatile("cp.async.cg.shared.global [%0], [%1], 16;" :: "r"(s), "l"(g));
}
#define CP_COMMIT() asm volatile("cp.async.commit_group;" ::: "memory")

__device__ __forceinline__ void mma8(float* c, const uint32_t* a, const uint32_t* b) {
    asm volatile(
        "mma.sync.aligned.m16n8k8.row.col.f32.tf32.tf32.f32 "
        "{%0,%1,%2,%3}, {%4,%5,%6,%7}, {%8,%9}, {%0,%1,%2,%3};"
        : "+f"(c[0]), "+f"(c[1]), "+f"(c[2]), "+f"(c[3])
        : "r"(a[0]), "r"(a[1]), "r"(a[2]), "r"(a[3]), "r"(b[0]), "r"(b[1]));
}

// ---------------------------------------------------------------------------
// tf32 tensor-core NT GEMM: C[M,N] = A[M,K] @ B[N,K]^T   (A,B K-major)
// BM=128, BK=32, 256 threads, cp.async double-buffered.
// flags: 1=relu, 2=tf32-round output.
// ---------------------------------------------------------------------------
#define BKP 36

template <int BN>
__global__ void __launch_bounds__(256, 2)
mma_gemm(const float* __restrict__ A, const float* __restrict__ B,
         float* __restrict__ C,
         const float* __restrict__ bias, const float* __restrict__ resid, int flags,
         int K, int lda, int ldb, int ldc,
         long long sAo, long long sAi, long long sBo, long long sBi,
         long long sCo, long long sCi, int zInner) {
    constexpr int WM = (BN == 128) ? 2 : 4;     // warps along M
    constexpr int WN = 8 / WM;                   // warps along N
    constexpr int MT = 128 / (WM * 16);          // m16 tiles per warp
    constexpr int NTL = BN / (WN * 8);           // n8 tiles per warp (=4)
    constexpr int STAGEF = (128 + BN) * BKP;     // floats per stage

    extern __shared__ float sm[];
    uint32_t sbase = smem_u32(sm);

    int tid = threadIdx.x;
    int wid = tid >> 5, lane = tid & 31;
    int t4 = lane >> 2, tq = lane & 3;
    int wm = wid % WM, wn = wid / WM;

    int z = blockIdx.z;
    int zo = z / zInner, zi = z - zo * zInner;
    A += (size_t)zo * sAo + (size_t)zi * sAi;
    B += (size_t)zo * sBo + (size_t)zi * sBi;
    size_t coff = (size_t)zo * sCo + (size_t)zi * sCi;
    C += coff;
    const float* Rp = resid ? resid + coff : nullptr;
    int bm = blockIdx.y * 128;
    int bn = blockIdx.x * BN;

    float acc[MT][NTL][4];
#pragma unroll
    for (int mi = 0; mi < MT; mi++)
#pragma unroll
        for (int ni = 0; ni < NTL; ni++)
#pragma unroll
            for (int j = 0; j < 4; j++) acc[mi][ni][j] = 0.f;

    int nk = K >> 5;

    auto load_stage = [&](int c, int s) {
        int k0 = c << 5;
        uint32_t ab = sbase + (uint32_t)(s * STAGEF) * 4u;
        uint32_t bb = ab + 128u * BKP * 4u;
#pragma unroll
        for (int it = 0; it < 4; it++) {
            int f = it * 256 + tid;
            int row = f >> 3, c4 = (f & 7) << 2;
            cp16(ab + (uint32_t)(row * BKP + c4) * 4u,
                 A + (size_t)(bm + row) * lda + k0 + c4);
        }
#pragma unroll
        for (int it = 0; it < BN / 32; it++) {
            int f = it * 256 + tid;
            int row = f >> 3, c4 = (f & 7) << 2;
            cp16(bb + (uint32_t)(row * BKP + c4) * 4u,
                 B + (size_t)(bn + row) * ldb + k0 + c4);
        }
        CP_COMMIT();
    };

    load_stage(0, 0);
    for (int c = 0; c < nk; c++) {
        int s = c & 1;
        if (c + 1 < nk) {
            load_stage(c + 1, (c + 1) & 1);
            asm volatile("cp.async.wait_group 1;" ::: "memory");
        } else {
            asm volatile("cp.async.wait_group 0;" ::: "memory");
        }
        __syncthreads();
        const float* Asp = sm + s * STAGEF;
        const float* Bsp = Asp + 128 * BKP;
#pragma unroll
        for (int ks = 0; ks < 4; ks++) {
            int k0 = ks * 8;
            uint32_t a[MT][4];
#pragma unroll
            for (int mi = 0; mi < MT; mi++) {
                int rb = wm * (MT * 16) + mi * 16 + t4;
                const float* p = Asp + rb * BKP + k0 + tq;
                a[mi][0] = __float_as_uint(p[0]);
                a[mi][1] = __float_as_uint(p[8 * BKP]);
                a[mi][2] = __float_as_uint(p[4]);
                a[mi][3] = __float_as_uint(p[8 * BKP + 4]);
            }
            uint32_t b[NTL][2];
#pragma unroll
            for (int ni = 0; ni < NTL; ni++) {
                int cb = wn * (NTL * 8) + ni * 8 + t4;
                const float* p = Bsp + cb * BKP + k0 + tq;
                b[ni][0] = __float_as_uint(p[0]);
                b[ni][1] = __float_as_uint(p[4]);
            }
#pragma unroll
            for (int mi = 0; mi < MT; mi++)
#pragma unroll
                for (int ni = 0; ni < NTL; ni++)
                    mma8(acc[mi][ni], a[mi], b[ni]);
        }
        __syncthreads();
    }

    // ---- epilogue: direct float2 stores ----
#pragma unroll
    for (int mi = 0; mi < MT; mi++) {
#pragma unroll
        for (int half = 0; half < 2; half++) {
            int row = bm + wm * (MT * 16) + mi * 16 + t4 + half * 8;
#pragma unroll
            for (int ni = 0; ni < NTL; ni++) {
                int col = bn + wn * (NTL * 8) + ni * 8 + tq * 2;
                float v0 = acc[mi][ni][half * 2 + 0];
                float v1 = acc[mi][ni][half * 2 + 1];
                if (bias) { v0 += bias[col]; v1 += bias[col + 1]; }
                if (Rp) {
                    float2 r = *(const float2*)(Rp + (size_t)row * ldc + col);
                    v0 += r.x; v1 += r.y;
                }
                if (flags & 1) { v0 = fmaxf(v0, 0.f); v1 = fmaxf(v1, 0.f); }
                if (flags & 2) { v0 = tf32r(v0); v1 = tf32r(v1); }
                *(float2*)(C + (size_t)row * ldc + col) = make_float2(v0, v1);
            }
        }
    }
}

// ---------------------------------------------------------------------------
// tf32 rounding copy (weights)
// ---------------------------------------------------------------------------
__global__ void cvt_kernel(const float* __restrict__ in, float* __restrict__ out, int n4) {
    int i = blockIdx.x * blockDim.x + threadIdx.x;
    if (i < n4) {
        float4 v = ((const float4*)in)[i];
        v.x = tf32r(v.x); v.y = tf32r(v.y); v.z = tf32r(v.z); v.w = tf32r(v.w);
        ((float4*)out)[i] = v;
    }
}

// ---------------------------------------------------------------------------
// LayerNorm (tf32-rounded output: feeds GEMMs)
// ---------------------------------------------------------------------------
__global__ void ln_kernel(const float* __restrict__ in, float* __restrict__ out,
                          const float* __restrict__ gam, const float* __restrict__ bet) {
    int row = blockIdx.x;
    int tid = threadIdx.x;
    const float* x = in + (size_t)row * DD;
    float4 v = *(const float4*)(x + tid * 4);
    float s = v.x + v.y + v.z + v.w;
    float ss = v.x * v.x + v.y * v.y + v.z * v.z + v.w * v.w;
    __shared__ float red[16];
#pragma unroll
    for (int o = 16; o; o >>= 1) {
        s += __shfl_xor_sync(0xffffffffu, s, o);
        ss += __shfl_xor_sync(0xffffffffu, ss, o);
    }
    if ((tid & 31) == 0) { red[(tid >> 5) * 2] = s; red[(tid >> 5) * 2 + 1] = ss; }
    __syncthreads();
    float mu = 0.f, m2 = 0.f;
#pragma unroll
    for (int w = 0; w < 8; w++) { mu += red[2 * w]; m2 += red[2 * w + 1]; }
    mu *= (1.0f / DD);
    float var = m2 * (1.0f / DD) - mu * mu;
    float rstd = rsqrtf(var + 1e-6f);
    float4 gg = *(const float4*)(gam + tid * 4);
    float4 bb = *(const float4*)(bet + tid * 4);
    float4 o4;
    o4.x = tf32r((v.x - mu) * rstd * gg.x + bb.x);
    o4.y = tf32r((v.y - mu) * rstd * gg.y + bb.y);
    o4.z = tf32r((v.z - mu) * rstd * gg.z + bb.z);
    o4.w = tf32r((v.w - mu) * rstd * gg.w + bb.w);
    *(float4*)(out + (size_t)row * DD + tid * 4) = o4;
}

// ---------------------------------------------------------------------------
// Fast software exp
// ---------------------------------------------------------------------------
__device__ __forceinline__ float fast_exp(float x) {
    x = fmaxf(x, -87.0f);
    float t = x * 1.4426950408889634f;
    float fi = floorf(t);
    float y = fmaf(fi, -0.6931471805599453f, x);
    int i = (int)fi;
    float p = 1.9841270e-4f;
    p = fmaf(p, y, 1.3888889e-3f);
    p = fmaf(p, y, 8.3333333e-3f);
    p = fmaf(p, y, 4.1666667e-2f);
    p = fmaf(p, y, 1.6666666e-1f);
    p = fmaf(p, y, 0.5f);
    p = fmaf(p, y, 1.0f);
    p = fmaf(p, y, 1.0f);
    return __int_as_float((i + 127) << 23) * p;
}

// ---------------------------------------------------------------------------
// In-place prior/mask/softmax (output tf32-rounded: feeds PV GEMM)
// ---------------------------------------------------------------------------
__device__ __forceinline__ float bred(float v, float* red, bool domax) {
#pragma unroll
    for (int o = 16; o; o >>= 1) {
        float t = __shfl_xor_sync(0xffffffffu, v, o);
        v = domax ? fmaxf(v, t) : v + t;
    }
    if ((threadIdx.x & 31) == 0) red[threadIdx.x >> 5] = v;
    __syncthreads();
    float r = red[0];
#pragma unroll
    for (int i = 1; i < 8; i++) r = domax ? fmaxf(r, red[i]) : r + red[i];
    __syncthreads();
    return r;
}

__global__ void softmax_kernel(float* __restrict__ attn,
                               const float* __restrict__ prior,
                               const int* __restrict__ mask) {
    int q = blockIdx.x;
    int b = blockIdx.y;
    int tid = threadIdx.x;
    __shared__ float red[8];

    const float* pr = prior + ((size_t)b * LL + q) * LL;
    float4 p0 = *(const float4*)(pr + tid * 4);
    float4 p1 = *(const float4*)(pr + 1024 + tid * 4);
    const int* mp = mask + b * LL;
    int4 m0 = *(const int4*)(mp + tid * 4);
    int4 m1 = *(const int4*)(mp + 1024 + tid * 4);

    float f[8];
    f[0] = 0.125f * p0.x; f[1] = 0.125f * p0.y; f[2] = 0.125f * p0.z; f[3] = 0.125f * p0.w;
    f[4] = 0.125f * p1.x; f[5] = 0.125f * p1.y; f[6] = 0.125f * p1.z; f[7] = 0.125f * p1.w;
    int mk[8] = {m0.x, m0.y, m0.z, m0.w, m1.x, m1.y, m1.z, m1.w};

    for (int h = 0; h < HH; h++) {
        float* srow = attn + (((size_t)(b * HH + h) * LL + q) * LL);
        float4 s0 = *(const float4*)(srow + tid * 4);
        float4 s1 = *(const float4*)(srow + 1024 + tid * 4);
        float v[8];
        v[0] = mk[0] ? s0.x * f[0] : -1e9f;
        v[1] = mk[1] ? s0.y * f[1] : -1e9f;
        v[2] = mk[2] ? s0.z * f[2] : -1e9f;
        v[3] = mk[3] ? s0.w * f[3] : -1e9f;
        v[4] = mk[4] ? s1.x * f[4] : -1e9f;
        v[5] = mk[5] ? s1.y * f[5] : -1e9f;
        v[6] = mk[6] ? s1.z * f[6] : -1e9f;
        v[7] = mk[7] ? s1.w * f[7] : -1e9f;
        float mloc = v[0];
#pragma unroll
        for (int i = 1; i < 8; i++) mloc = fmaxf(mloc, v[i]);
        float M = bred(mloc, red, true);
        float e[8];
        float ssum = 0.f;
#pragma unroll
        for (int i = 0; i < 8; i++) { e[i] = fast_exp(v[i] - M); ssum += e[i]; }
        float S = bred(ssum, red, false);
        float inv = 1.0f / S;
        float4 o0 = make_float4(tf32r(e[0] * inv), tf32r(e[1] * inv),
                                tf32r(e[2] * inv), tf32r(e[3] * inv));
        float4 o1 = make_float4(tf32r(e[4] * inv), tf32r(e[5] * inv),
                                tf32r(e[6] * inv), tf32r(e[7] * inv));
        *(float4*)(srow + tid * 4) = o0;
        *(float4*)(srow + 1024 + tid * 4) = o1;
    }
}

// ---------------------------------------------------------------------------
// Launch
// ---------------------------------------------------------------------------
#define SMEM_128 ((128 + 128) * BKP * 4 * 2)    // 73728
#define SMEM_64  ((128 + 64) * BKP * 4 * 2)     // 55296

extern "C" void kernel_launch(void* const* d_in, const int* in_sizes, int n_in,
                              void* d_out, int out_size) {
    const float* src    = (const float*)d_in[0];
    const int*   mask   = (const int*)d_in[1];
    const float* prior  = (const float*)d_in[2];
    const float* ln1_g  = (const float*)d_in[3];
    const float* ln1_b  = (const float*)d_in[4];
    const float* wq     = (const float*)d_in[5];
    const float* wk     = (const float*)d_in[6];
    const float* wv     = (const float*)d_in[7];
    const float* fc_w   = (const float*)d_in[8];
    const float* ln2_g  = (const float*)d_in[9];
    const float* ln2_b  = (const float*)d_in[10];
    const float* w1_w   = (const float*)d_in[11];
    const float* w1_b   = (const float*)d_in[12];
    const float* w2_w   = (const float*)d_in[13];
    const float* w2_b   = (const float*)d_in[14];

    float* yout = (float*)d_out;
    float* attn = yout + Y_ELEMS;

    float* xb;  cudaGetSymbolAddress((void**)&xb, g_x);
    float* qb;  cudaGetSymbolAddress((void**)&qb, g_q);
    float* kb;  cudaGetSymbolAddress((void**)&kb, g_k);
    float* vtb; cudaGetSymbolAddress((void**)&vtb, g_vt);
    float* ob;  cudaGetSymbolAddress((void**)&ob, g_o);
    float* yb;  cudaGetSymbolAddress((void**)&yb, g_y);
    float* zb;  cudaGetSymbolAddress((void**)&zb, g_z);
    float* hb;  cudaGetSymbolAddress((void**)&hb, g_h);
    float* wqc; cudaGetSymbolAddress((void**)&wqc, g_wq);
    float* wkc; cudaGetSymbolAddress((void**)&wkc, g_wk);
    float* wvc; cudaGetSymbolAddress((void**)&wvc, g_wv);
    float* fcc; cudaGetSymbolAddress((void**)&fcc, g_fc);
    float* w1c; cudaGetSymbolAddress((void**)&w1c, g_w1);
    float* w2c; cudaGetSymbolAddress((void**)&w2c, g_w2);

    cudaFuncSetAttribute(mma_gemm<128>, cudaFuncAttributeMaxDynamicSharedMemorySize, SMEM_128);
    cudaFuncSetAttribute(mma_gemm<64>,  cudaFuncAttributeMaxDynamicSharedMemorySize, SMEM_64);

    // 0) round weights to tf32
    cvt_kernel<<<(DD * DD / 4 + 255) / 256, 256>>>(wq, wqc, DD * DD / 4);
    cvt_kernel<<<(DD * DD / 4 + 255) / 256, 256>>>(wk, wkc, DD * DD / 4);
    cvt_kernel<<<(DD * DD / 4 + 255) / 256, 256>>>(wv, wvc, DD * DD / 4);
    cvt_kernel<<<(DD * DD / 4 + 255) / 256, 256>>>(fc_w, fcc, DD * DD / 4);
    cvt_kernel<<<(DFF * DD / 4 + 255) / 256, 256>>>(w1_w, w1c, DFF * DD / 4);
    cvt_kernel<<<(DFF * DD / 4 + 255) / 256, 256>>>(w2_w, w2c, DFF * DD / 4);

    // 1) LN1 (tf32-rounded)
    ln_kernel<<<ROWS, 256>>>(src, xb, ln1_g, ln1_b);

    // 2) Q, K projections (tf32-rounded outputs)
    {
        dim3 g(DD / 128, ROWS / 128, 1);
        mma_gemm<128><<<g, 256, SMEM_128>>>(xb, wqc, qb, nullptr, nullptr, 2,
            DD, DD, DD, DD, 0, 0, 0, 0, 0, 0, 1);
        mma_gemm<128><<<g, 256, SMEM_128>>>(xb, wkc, kb, nullptr, nullptr, 2,
            DD, DD, DD, DD, 0, 0, 0, 0, 0, 0, 1);
    }
    // 2b) V transposed: Vt[H*DV, ROWS] = wv @ x^T
    {
        dim3 g(ROWS / 128, DD / 128, 1);
        mma_gemm<128><<<g, 256, SMEM_128>>>(wvc, xb, vtb, nullptr, nullptr, 2,
            DD, DD, DD, ROWS, 0, 0, 0, 0, 0, 0, 1);
    }

    // 3) Scores S = q . k per (b,h), into attn region
    {
        dim3 g(LL / 128, LL / 128, BB * HH);
        mma_gemm<128><<<g, 256, SMEM_128>>>(qb, kb, attn, nullptr, nullptr, 0,
            DK, DD, DD, LL,
            (long long)LL * DD, (long long)DK,
            (long long)LL * DD, (long long)DK,
            (long long)HH * LL * LL, (long long)LL * LL,
            HH);
    }

    // 4) prior * mask * softmax (in place, tf32-rounded)
    softmax_kernel<<<dim3(LL, BB), 256>>>(attn, prior, mask);

    // 5) O = P @ Vt^T per (b,h): M=2048, N=64, K=2048
    {
        dim3 g(1, LL / 128, BB * HH);
        mma_gemm<64><<<g, 256, SMEM_64>>>(attn, vtb, ob, nullptr, nullptr, 2,
            LL, LL, ROWS, DD,
            (long long)HH * LL * LL, (long long)LL * LL,   // A: b, h
            (long long)LL, (long long)DV * ROWS,           // B: b (col), h (row)
            (long long)LL * DD, (long long)DV,             // C: b, h
            HH);
    }

    // 6) y = O @ fc^T + src
    {
        dim3 g(DD / 128, ROWS / 128, 1);
        mma_gemm<128><<<g, 256, SMEM_128>>>(ob, fcc, yb, nullptr, src, 0,
            DD, DD, DD, DD, 0, 0, 0, 0, 0, 0, 1);
    }

    // 7) LN2 (tf32-rounded)
    ln_kernel<<<ROWS, 256>>>(yb, zb, ln2_g, ln2_b);

    // 8) h = relu(z @ w1^T + b1), tf32-rounded
    {
        dim3 g(DFF / 128, ROWS / 128, 1);
        mma_gemm<128><<<g, 256, SMEM_128>>>(zb, w1c, hb, w1_b, nullptr, 1 | 2,
            DD, DD, DD, DFF, 0, 0, 0, 0, 0, 0, 1);
    }

    // 9) y_out = h @ w2^T + b2 + y
    {
        dim3 g(DD / 128, ROWS / 128, 1);
        mma_gemm<128><<<g, 256, SMEM_128>>>(hb, w2c, yout, w2_b, yb, 0,
            DFF, DFF, DFF, DD, 0, 0, 0, 0, 0, 0, 1);
    }
}